// round 14
// baseline (speedup 1.0000x reference)
#include <cuda_runtime.h>
#include <cuda_fp16.h>
#include <cstdint>

#define B_ 4
#define N_ 4096
#define C_ 256
#define NSPLIT 32
#define M_ (B_*N_)
#define L2E 1.4426950408889634f

// ---- attention smem layout (bytes) ----
#define QS_OFF   0          // 64x512 = 32768
#define KS_OFF   32768      // 2 x 32768
#define VTS_OFF  98304      // 2 x 32768
#define PS_OFF   163840     // 2 x 8192 (reused for Z exchange)
#define SMEM_ATT 180224

// ---- k_qkv smem layout (bytes) ----
#define QA_OFF   0          // 2 x 8192   (A chunk double buffer)
#define QW_OFF   16384      // 2 x 32768  (W chunk double buffer)
#define SMEM_QKV 81920

// ---------------- device scratch ----------------
__device__ float g_psum[2*B_*NSPLIT*C_];
__device__ float g_psq [2*B_*NSPLIT*C_];
__device__ float g_mean[2*B_*C_];
__device__ float g_rstd[2*B_*C_];
__device__ __half g_Wth[3*C_*C_];           // W^T fp16: [which][n][k]
__device__ __half g_Qh[M_*C_];              // l2norm'd, pre-scaled by log2(e)
__device__ __half g_Kh[M_*C_];              // l2norm'd
__device__ __half g_VTh[B_*C_*N_];          // [b][c][n]

typedef unsigned long long ull;

// ---------------- PTX helpers ----------------
__device__ __forceinline__ uint32_t s2u(const void* p){
    uint32_t a;
    asm("{ .reg .u64 t; cvta.to.shared.u64 t, %1; cvt.u32.u64 %0, t; }" : "=r"(a) : "l"(p));
    return a;
}
__device__ __forceinline__ void ldm4(uint32_t a, uint32_t& r0, uint32_t& r1,
                                     uint32_t& r2, uint32_t& r3){
    asm volatile("ldmatrix.sync.aligned.m8n8.x4.shared.b16 {%0,%1,%2,%3}, [%4];"
        : "=r"(r0), "=r"(r1), "=r"(r2), "=r"(r3) : "r"(a));
}
__device__ __forceinline__ void mma16816(float* d, uint32_t a0, uint32_t a1,
                                         uint32_t a2, uint32_t a3,
                                         uint32_t b0, uint32_t b1){
    asm volatile("mma.sync.aligned.m16n8k16.row.col.f32.f16.f16.f32 "
        "{%0,%1,%2,%3},{%4,%5,%6,%7},{%8,%9},{%0,%1,%2,%3};"
        : "+f"(d[0]), "+f"(d[1]), "+f"(d[2]), "+f"(d[3])
        : "r"(a0), "r"(a1), "r"(a2), "r"(a3), "r"(b0), "r"(b1));
}
// fp16-accumulator variant: D/C are 2 x f16x2 regs
__device__ __forceinline__ void mma16816h(uint32_t* d, uint32_t a0, uint32_t a1,
                                          uint32_t a2, uint32_t a3,
                                          uint32_t b0, uint32_t b1){
    asm volatile("mma.sync.aligned.m16n8k16.row.col.f16.f16.f16.f16 "
        "{%0,%1},{%2,%3,%4,%5},{%6,%7},{%0,%1};"
        : "+r"(d[0]), "+r"(d[1])
        : "r"(a0), "r"(a1), "r"(a2), "r"(a3), "r"(b0), "r"(b1));
}
__device__ __forceinline__ void cpa16(uint32_t s, const void* g){
    asm volatile("cp.async.cg.shared.global [%0], [%1], 16;" :: "r"(s), "l"(g));
}
#define CPCOMMIT() asm volatile("cp.async.commit_group;")
#define CPWAIT(n)  asm volatile("cp.async.wait_group %0;" :: "n"(n))

__device__ __forceinline__ uint32_t ex2h2(uint32_t h){
    uint32_t r; asm("ex2.approx.f16x2 %0, %1;" : "=r"(r) : "r"(h)); return r;
}
__device__ __forceinline__ uint32_t sqr2(uint32_t v){
    uint32_t r; asm("mul.rn.f16x2 %0, %1, %1;" : "=r"(r) : "r"(v)); return r;
}
__device__ __forceinline__ float hsum2(uint32_t h2){
    __half2 h = *(__half2*)&h2;
    float2 f = __half22float2(h);
    return f.x + f.y;
}

// ---------------- instance-norm statistics ----------------
__global__ void k_stats_partial(const float* __restrict__ content,
                                const float* __restrict__ style){
    const float* x = blockIdx.z ? style : content;
    const int b = blockIdx.y, sp = blockIdx.x, c = threadIdx.x;
    const int rows = N_ / NSPLIT;
    const float* base = x + (size_t)b*N_*C_ + (size_t)sp*rows*C_ + c;
    float s = 0.f, ss = 0.f;
    #pragma unroll 4
    for (int r = 0; r < rows; r++){
        float v = base[(size_t)r*C_];
        s += v; ss += v*v;
    }
    int idx = ((blockIdx.z*B_ + b)*NSPLIT + sp)*C_ + c;
    g_psum[idx] = s; g_psq[idx] = ss;
}

__global__ void k_stats_final(){
    const int b = blockIdx.x, t = blockIdx.y, c = threadIdx.x;
    float s = 0.f, ss = 0.f;
    #pragma unroll
    for (int sp = 0; sp < NSPLIT; sp++){
        int idx = ((t*B_ + b)*NSPLIT + sp)*C_ + c;
        s += g_psum[idx]; ss += g_psq[idx];
    }
    float mean = s * (1.f/N_);
    float var  = fmaxf(ss * (1.f/N_) - mean*mean, 0.f);
    g_mean[(t*B_ + b)*C_ + c] = mean;
    g_rstd[(t*B_ + b)*C_ + c] = rsqrtf(var + 1e-5f);
}

// ---------------- W transpose + fp16 convert ----------------
__global__ void k_wcvt(const float* __restrict__ Wq, const float* __restrict__ Wk,
                       const float* __restrict__ Wv){
    __shared__ float t[32][33];
    const float* W = (blockIdx.z == 0) ? Wq : (blockIdx.z == 1) ? Wk : Wv;
    __half* O = g_Wth + (size_t)blockIdx.z*C_*C_;
    const int k0 = blockIdx.x << 5, n0 = blockIdx.y << 5;
    for (int i = threadIdx.y; i < 32; i += 8)
        t[i][threadIdx.x] = W[(size_t)(k0 + i)*C_ + n0 + threadIdx.x];
    __syncthreads();
    for (int i = threadIdx.y; i < 32; i += 8)
        O[(size_t)(n0 + i)*C_ + k0 + threadIdx.x] = __float2half_rn(t[threadIdx.x][i]);
}

// ---------------- fused norm + 1x1 conv (fp16 HMMA), pipelined ---------------
// grid (M_/64, 3): which = 0 Q (l2norm*log2e), 1 K (l2norm), 2 V (transpose)
__global__ __launch_bounds__(256, 2) void k_qkv(const float* __restrict__ content,
                                                const float* __restrict__ style,
                                                const float* __restrict__ bq,
                                                const float* __restrict__ bk,
                                                const float* __restrict__ bv){
    __shared__ __align__(16) char smem[SMEM_QKV];
    const uint32_t sb = s2u(smem);
    const int tid = threadIdx.x, warp = tid >> 5, lane = tid & 31;
    const int wq2 = warp >> 2, wc4 = warp & 3;
    const int mi = lane >> 3, r8 = lane & 7, l4 = lane >> 2, l2 = lane & 3;
    const int which = blockIdx.y;
    const int tm = blockIdx.x << 6;
    const int b = tm >> 12;
    const float* A = (which == 0) ? content : style;
    const float* bias = (which == 0) ? bq : (which == 1) ? bk : bv;
    const __half* wsrc = g_Wth + (size_t)which*C_*C_;
    const float* meanp = g_mean + (which == 1 ? B_*C_ : 0) + b*C_;
    const float* rstdp = g_rstd + (which == 1 ? B_*C_ : 0) + b*C_;
    const bool donorm = which < 2;

    const int ar0 = tid >> 4;            // base row (+16*i)
    const int ac4 = tid & 15;            // channel quad within chunk

    float acc[2][8][4];
    #pragma unroll
    for (int mt = 0; mt < 2; mt++)
        #pragma unroll
        for (int ct = 0; ct < 8; ct++){
            acc[mt][ct][0] = 0.f; acc[mt][ct][1] = 0.f;
            acc[mt][ct][2] = 0.f; acc[mt][ct][3] = 0.f;
        }

    // prologue: W(0) cp.async, A(0) -> regs
    for (int it = tid; it < 2048; it += 256){
        int n = it >> 3, c16 = it & 7;
        cpa16(sb + QW_OFF + n*128 + (((uint32_t)(c16 ^ (n & 7))) << 4),
              wsrc + (size_t)n*C_ + (c16 << 3));
    }
    CPCOMMIT();
    float4 av[4];
    #pragma unroll
    for (int i = 0; i < 4; i++)
        av[i] = *(const float4*)(A + (size_t)(tm + ar0 + (i << 4))*C_ + (ac4 << 2));

    for (int kc = 0; kc < 4; kc++){
        __syncthreads();
        {
            const int cc = (kc << 6) + (ac4 << 2);
            float4 mn, rs;
            if (donorm){ mn = *(const float4*)(meanp + cc); rs = *(const float4*)(rstdp + cc); }
            char* ab = smem + QA_OFF + (kc & 1)*8192;
            #pragma unroll
            for (int i = 0; i < 4; i++){
                float4 v = av[i];
                if (donorm){
                    v.x = (v.x - mn.x)*rs.x; v.y = (v.y - mn.y)*rs.y;
                    v.z = (v.z - mn.z)*rs.z; v.w = (v.w - mn.w)*rs.w;
                }
                __half2 h0 = __floats2half2_rn(v.x, v.y);
                __half2 h1 = __floats2half2_rn(v.z, v.w);
                uint2 u; u.x = *(uint32_t*)&h0; u.y = *(uint32_t*)&h1;
                int r = ar0 + (i << 4);
                int c16 = ac4 >> 1, sub = ac4 & 1;
                *(uint2*)(ab + (r << 7) + ((c16 ^ (r & 7)) << 4) + (sub << 3)) = u;
            }
        }
        if (kc < 3){
            for (int it = tid; it < 2048; it += 256){
                int n = it >> 3, c16 = it & 7;
                cpa16(sb + QW_OFF + ((kc + 1) & 1)*32768 + n*128 + (((uint32_t)(c16 ^ (n & 7))) << 4),
                      wsrc + (size_t)n*C_ + ((kc + 1) << 6) + (c16 << 3));
            }
            CPCOMMIT();
            #pragma unroll
            for (int i = 0; i < 4; i++)
                av[i] = *(const float4*)(A + (size_t)(tm + ar0 + (i << 4))*C_ + ((kc + 1) << 6) + (ac4 << 2));
            CPWAIT(1);
        } else {
            CPWAIT(0);
        }
        __syncthreads();

        const uint32_t abase = sb + QA_OFF + (kc & 1)*8192;
        const uint32_t wbase = sb + QW_OFF + (kc & 1)*32768;
        #pragma unroll
        for (int cs = 0; cs < 4; cs++){
            uint32_t colA = ((uint32_t)((2*cs + (mi >> 1)) ^ r8)) << 4;
            uint32_t a00,a01,a02,a03, a10,a11,a12,a13;
            uint32_t aAb = abase + (uint32_t)((wq2 << 5) + r8 + ((mi & 1) << 3))*128;
            ldm4(aAb + colA, a00,a01,a02,a03);
            ldm4(aAb + 16*128 + colA, a10,a11,a12,a13);
            uint32_t colB = ((uint32_t)((2*cs + (mi & 1)) ^ r8)) << 4;
            #pragma unroll
            for (int ctp = 0; ctp < 4; ctp++){
                uint32_t w0,w1,w2,w3;
                ldm4(wbase + (uint32_t)((wc4 << 6) + (ctp << 4) + r8 + ((mi >> 1) << 3))*128 + colB,
                     w0,w1,w2,w3);
                mma16816(acc[0][2*ctp],   a00,a01,a02,a03, w0,w1);
                mma16816(acc[0][2*ctp+1], a00,a01,a02,a03, w2,w3);
                mma16816(acc[1][2*ctp],   a10,a11,a12,a13, w0,w1);
                mma16816(acc[1][2*ctp+1], a10,a11,a12,a13, w2,w3);
            }
        }
    }
    __syncthreads();

    float ssq[2][2] = {{0.f,0.f},{0.f,0.f}};
    #pragma unroll
    for (int mt = 0; mt < 2; mt++)
        #pragma unroll
        for (int ct = 0; ct < 8; ct++){
            int ch = (wc4 << 6) + (ct << 3) + (l2 << 1);
            float2 bb = *(const float2*)(bias + ch);
            acc[mt][ct][0] += bb.x; acc[mt][ct][1] += bb.y;
            acc[mt][ct][2] += bb.x; acc[mt][ct][3] += bb.y;
            if (which < 2){
                ssq[mt][0] += acc[mt][ct][0]*acc[mt][ct][0] + acc[mt][ct][1]*acc[mt][ct][1];
                ssq[mt][1] += acc[mt][ct][2]*acc[mt][ct][2] + acc[mt][ct][3]*acc[mt][ct][3];
            }
        }

    if (which < 2){
        #pragma unroll
        for (int mt = 0; mt < 2; mt++)
            #pragma unroll
            for (int h = 0; h < 2; h++){
                float v = ssq[mt][h];
                v += __shfl_xor_sync(0xffffffffu, v, 1);
                v += __shfl_xor_sync(0xffffffffu, v, 2);
                ssq[mt][h] = v;
            }
        float* ssm = (float*)smem;    // [4][64]
        if (l2 == 0){
            #pragma unroll
            for (int mt = 0; mt < 2; mt++){
                int rl = (wq2 << 5) + (mt << 4) + l4;
                ssm[wc4*64 + rl]     = ssq[mt][0];
                ssm[wc4*64 + rl + 8] = ssq[mt][1];
            }
        }
        __syncthreads();
        const float qsc = (which == 0) ? L2E : 1.f;
        __half* O = (which == 0) ? g_Qh : g_Kh;
        #pragma unroll
        for (int mt = 0; mt < 2; mt++){
            int rl = (wq2 << 5) + (mt << 4) + l4;
            float scl = rsqrtf(ssm[rl] + ssm[64+rl] + ssm[128+rl] + ssm[192+rl] + 1e-12f) * qsc;
            int rh = rl + 8;
            float sch = rsqrtf(ssm[rh] + ssm[64+rh] + ssm[128+rh] + ssm[192+rh] + 1e-12f) * qsc;
            #pragma unroll
            for (int ct = 0; ct < 8; ct++){
                int ch = (wc4 << 6) + (ct << 3) + (l2 << 1);
                __half2 h = __floats2half2_rn(acc[mt][ct][0]*scl, acc[mt][ct][1]*scl);
                *(uint32_t*)(O + (size_t)(tm + rl)*C_ + ch) = *(uint32_t*)&h;
                h = __floats2half2_rn(acc[mt][ct][2]*sch, acc[mt][ct][3]*sch);
                *(uint32_t*)(O + (size_t)(tm + rh)*C_ + ch) = *(uint32_t*)&h;
            }
        }
    } else {
        __half* T = (__half*)smem;    // [64][264]
        #pragma unroll
        for (int mt = 0; mt < 2; mt++){
            int rl = (wq2 << 5) + (mt << 4) + l4, rh = rl + 8;
            #pragma unroll
            for (int ct = 0; ct < 8; ct++){
                int ch = (wc4 << 6) + (ct << 3) + (l2 << 1);
                __half2 h = __floats2half2_rn(acc[mt][ct][0], acc[mt][ct][1]);
                *(uint32_t*)&T[rl*264 + ch] = *(uint32_t*)&h;
                h = __floats2half2_rn(acc[mt][ct][2], acc[mt][ct][3]);
                *(uint32_t*)&T[rh*264 + ch] = *(uint32_t*)&h;
            }
        }
        __syncthreads();
        const int c = tid;
        const int n0 = tm & (N_ - 1);
        __half* Ov = g_VTh + ((size_t)(b*C_ + c))*N_ + n0;
        #pragma unroll
        for (int j = 0; j < 8; j++){
            __half hh[8];
            #pragma unroll
            for (int i = 0; i < 8; i++) hh[i] = T[(j*8 + i)*264 + c];
            *(uint4*)(Ov + j*8) = *(uint4*)hh;
        }
    }
}

// ---------------- HMMA fused attention + AdaIN (fp16-accum A, no Q hoist) ----
// CTA = 64 queries x 256 channels x all 4096 keys. 256 threads (8 warps).
__global__ __launch_bounds__(256, 1) void k_attn_mma(const float* __restrict__ content,
                                                     float* __restrict__ out){
    extern __shared__ char sm[];
    const uint32_t sb = s2u(sm);
    const int tid = threadIdx.x, warp = tid >> 5, lane = tid & 31;
    const int q0 = blockIdx.x << 6;
    const int b  = q0 >> 12;
    const int wq = warp & 3, wk2 = warp >> 2;        // phase A tiling (16q x 32k)
    const int wq2 = warp >> 2, wc4 = warp & 3;       // phase B tiling (32q x 64ch)
    const int mi = lane >> 3, r8 = lane & 7;
    const int l4 = lane >> 2, l2 = lane & 3;

    const __half* vt_base = g_VTh + (size_t)b*C_*N_;
    const uint32_t aA     = sb + QS_OFF + (uint32_t)((wq << 4) + r8 + ((mi & 1) << 3))*512;
    const uint32_t aB_off = (uint32_t)((wk2 << 5) + r8 + ((mi >> 1) << 3))*512;
    const uint32_t pB_off = (uint32_t)((wq2 << 5) + r8 + ((mi & 1) << 3))*128;
    const uint32_t vB_off = (uint32_t)((wc4 << 6) + r8 + ((mi >> 1) << 3))*128;

    float accM[2][8][4], accV2[2][8][4];
    #pragma unroll
    for (int mt = 0; mt < 2; mt++)
        #pragma unroll
        for (int ct = 0; ct < 8; ct++)
            #pragma unroll
            for (int j = 0; j < 4; j++){ accM[mt][ct][j] = 0.f; accV2[mt][ct][j] = 0.f; }
    float z0 = 0.f, z1 = 0.f;

    auto loadK = [&](int kt, int buf){
        uint32_t kdst = sb + KS_OFF + buf*32768;
        for (int it = tid; it < 2048; it += 256){
            int r = it >> 5, c16 = it & 31;
            cpa16(kdst + r*512 + (((uint32_t)(c16 ^ (r & 7))) << 4),
                  g_Kh + (((size_t)((b << 12) + (kt << 6) + r)) << 8) + (c16 << 3));
        }
    };
    auto loadVT = [&](int kt, int buf){
        uint32_t vdst = sb + VTS_OFF + buf*32768;
        for (int it = tid; it < 2048; it += 256){
            int r = it >> 3, c16 = it & 7;
            cpa16(vdst + r*128 + (((uint32_t)(c16 ^ (r & 7))) << 4),
                  vt_base + (((size_t)r) << 12) + (kt << 6) + (c16 << 3));
        }
    };
    // fp16 logits dd[nt][0]=rows r (c0,c1), dd[nt][1]=rows r+8 -> exp -> P store
    auto expStore = [&](uint32_t dd[4][2], int j){
        char* pb = sm + PS_OFF + (j & 1)*8192;
        const int qlo = (wq << 4) + l4;
        #pragma unroll
        for (int nt = 0; nt < 4; nt++){
            uint32_t plo = ex2h2(dd[nt][0]);
            uint32_t phi = ex2h2(dd[nt][1]);
            z0 += hsum2(plo);
            z1 += hsum2(phi);
            int c16p = (wk2 << 2) + nt;
            uint32_t sw = ((uint32_t)(c16p ^ l4)) << 4;
            *(uint32_t*)(pb + qlo*128 + sw + (l2 << 2))       = plo;
            *(uint32_t*)(pb + (qlo + 8)*128 + sw + (l2 << 2)) = phi;
        }
    };
    auto phaseBs = [&](uint32_t aPb, uint32_t aVb, int s){
        uint32_t colA = ((uint32_t)((2*s + (mi >> 1)) ^ r8)) << 4;
        uint32_t p00,p01,p02,p03, p10,p11,p12,p13;
        ldm4(aPb + colA, p00,p01,p02,p03);
        ldm4(aPb + 16*128 + colA, p10,p11,p12,p13);
        uint32_t colB = ((uint32_t)((2*s + (mi & 1)) ^ r8)) << 4;
        #pragma unroll
        for (int ctp = 0; ctp < 4; ctp++){
            uint32_t v0,v1,v2,v3;
            ldm4(aVb + (uint32_t)(ctp << 4)*128 + colB, v0,v1,v2,v3);
            mma16816(accM[0][2*ctp],   p00,p01,p02,p03, v0,v1);
            mma16816(accM[0][2*ctp+1], p00,p01,p02,p03, v2,v3);
            mma16816(accM[1][2*ctp],   p10,p11,p12,p13, v0,v1);
            mma16816(accM[1][2*ctp+1], p10,p11,p12,p13, v2,v3);
            uint32_t w0 = sqr2(v0), w1 = sqr2(v1), w2 = sqr2(v2), w3 = sqr2(v3);
            mma16816(accV2[0][2*ctp],   p00,p01,p02,p03, w0,w1);
            mma16816(accV2[0][2*ctp+1], p00,p01,p02,p03, w2,w3);
            mma16816(accV2[1][2*ctp],   p10,p11,p12,p13, w0,w1);
            mma16816(accV2[1][2*ctp+1], p10,p11,p12,p13, w2,w3);
        }
    };

    // ---- prologue ----
    for (int it = tid; it < 2048; it += 256){
        int r = it >> 5, c16 = it & 31;
        cpa16(sb + QS_OFF + r*512 + (((uint32_t)(c16 ^ (r & 7))) << 4),
              g_Qh + (((size_t)(q0 + r)) << 8) + (c16 << 3));
    }
    loadK(0, 0);
    CPCOMMIT();                 // G0: Q + K(0)
    loadVT(0, 0);
    loadK(1, 1);
    CPCOMMIT();                 // G1: VT(0) + K(1)
    CPWAIT(1);                  // G0 complete
    __syncthreads();

    {   // phase A(0) -> P[0]  (fp16 accumulation)
        const uint32_t kb0 = sb + KS_OFF + aB_off;
        uint32_t dd[4][2];
        #pragma unroll
        for (int i = 0; i < 4; i++){ dd[i][0] = 0u; dd[i][1] = 0u; }
        #pragma unroll
        for (int cs = 0; cs < 16; cs++){
            uint32_t a0,a1,a2,a3, b0,b1,b2,b3;
            ldm4(aA + (((uint32_t)((2*cs + (mi >> 1)) ^ r8)) << 4), a0,a1,a2,a3);
            uint32_t cB = ((uint32_t)((2*cs + (mi & 1)) ^ r8)) << 4;
            ldm4(kb0 + cB, b0,b1,b2,b3);
            mma16816h(dd[0], a0,a1,a2,a3, b0,b1);
            mma16816h(dd[1], a0,a1,a2,a3, b2,b3);
            ldm4(kb0 + 16*512 + cB, b0,b1,b2,b3);
            mma16816h(dd[2], a0,a1,a2,a3, b0,b1);
            mma16816h(dd[3], a0,a1,a2,a3, b2,b3);
        }
        expStore(dd, 0);
    }

    // ---- main loop: 63 fused iterations, A(i+1) interleaved with B(i) ----
    for (int i = 0; i < 63; i++){
        CPWAIT(0);              // K(i+1), VT(i) complete
        __syncthreads();        // load visibility + P(i) stores + buffer reuse
        if (i < 62) loadK(i + 2, i & 1);
        loadVT(i + 1, (i + 1) & 1);
        CPCOMMIT();

        const uint32_t kb0 = sb + KS_OFF + ((i + 1) & 1)*32768 + aB_off;
        const uint32_t aPb = sb + PS_OFF  + (i & 1)*8192  + pB_off;
        const uint32_t aVb = sb + VTS_OFF + (i & 1)*32768 + vB_off;
        uint32_t dd[4][2];
        #pragma unroll
        for (int k = 0; k < 4; k++){ dd[k][0] = 0u; dd[k][1] = 0u; }

        #pragma unroll
        for (int s = 0; s < 4; s++){
            // -- A chunk: k-steps 4s..4s+3 on K[(i+1)&1] (fp16 accum) --
            #pragma unroll
            for (int c = 0; c < 4; c++){
                const int cs = 4*s + c;
                uint32_t a0,a1,a2,a3, b0,b1,b2,b3;
                ldm4(aA + (((uint32_t)((2*cs + (mi >> 1)) ^ r8)) << 4), a0,a1,a2,a3);
                uint32_t cB = ((uint32_t)((2*cs + (mi & 1)) ^ r8)) << 4;
                ldm4(kb0 + cB, b0,b1,b2,b3);
                mma16816h(dd[0], a0,a1,a2,a3, b0,b1);
                mma16816h(dd[1], a0,a1,a2,a3, b2,b3);
                ldm4(kb0 + 16*512 + cB, b0,b1,b2,b3);
                mma16816h(dd[2], a0,a1,a2,a3, b0,b1);
                mma16816h(dd[3], a0,a1,a2,a3, b2,b3);
            }
            // -- B chunk s: P[i&1] x VT[i&1] (independent stream) --
            phaseBs(aPb, aVb, s);
        }
        expStore(dd, i + 1);    // P[(i+1)&1]
    }

    // ---- final tile: B(63) only ----
    CPWAIT(0);
    __syncthreads();
    {
        const uint32_t aPb = sb + PS_OFF  + (63 & 1)*8192  + pB_off;
        const uint32_t aVb = sb + VTS_OFF + (63 & 1)*32768 + vB_off;
        #pragma unroll
        for (int s = 0; s < 4; s++) phaseBs(aPb, aVb, s);
    }
    __syncthreads();            // P buffers free for Z exchange

    // ---- Z exchange: reduce over l2 lanes, then across wk2 via smem ----
    z0 += __shfl_xor_sync(0xffffffffu, z0, 1);
    z0 += __shfl_xor_sync(0xffffffffu, z0, 2);
    z1 += __shfl_xor_sync(0xffffffffu, z1, 1);
    z1 += __shfl_xor_sync(0xffffffffu, z1, 2);
    float* Zs = (float*)(sm + PS_OFF);      // [64][2]
    if (l2 == 0){
        Zs[(((wq << 4) + l4) << 1) + wk2]     = z0;
        Zs[(((wq << 4) + l4 + 8) << 1) + wk2] = z1;
    }
    __syncthreads();

    // ---- epilogue: M/S2, AdaIN, store ----
    const float* meanp = g_mean + b*C_;
    const float* rstdp = g_rstd + b*C_;
    #pragma unroll
    for (int mt = 0; mt < 2; mt++){
        const int rloc = (wq2 << 5) + (mt << 4) + l4;
        const float izlo = 1.f / (Zs[rloc << 1] + Zs[(rloc << 1) + 1]);
        const float izhi = 1.f / (Zs[(rloc + 8) << 1] + Zs[((rloc + 8) << 1) + 1]);
        const int rl = q0 + rloc;
        const size_t glo = ((size_t)rl) << 8;
        const size_t ghi = ((size_t)(rl + 8)) << 8;
        #pragma unroll
        for (int ct = 0; ct < 8; ct++){
            const int ch = (wc4 << 6) + (ct << 3) + (l2 << 1);
            const float mn0 = meanp[ch], mn1 = meanp[ch+1];
            const float rs0 = rstdp[ch], rs1 = rstdp[ch+1];
            {
                float2 cv = *(const float2*)(content + glo + ch);
                float m = accM[mt][ct][0]*izlo;
                float s2 = accV2[mt][ct][0]*izlo - m*m;
                float s = s2 > 0.f ? sqrtf(s2) : 0.f;
                float2 o;
                o.x = s*((cv.x - mn0)*rs0) + m;
                m = accM[mt][ct][1]*izlo;
                s2 = accV2[mt][ct][1]*izlo - m*m;
                s = s2 > 0.f ? sqrtf(s2) : 0.f;
                o.y = s*((cv.y - mn1)*rs1) + m;
                *(float2*)(out + glo + ch) = o;
            }
            {
                float2 cv = *(const float2*)(content + ghi + ch);
                float m = accM[mt][ct][2]*izhi;
                float s2 = accV2[mt][ct][2]*izhi - m*m;
                float s = s2 > 0.f ? sqrtf(s2) : 0.f;
                float2 o;
                o.x = s*((cv.x - mn0)*rs0) + m;
                m = accM[mt][ct][3]*izhi;
                s2 = accV2[mt][ct][3]*izhi - m*m;
                s = s2 > 0.f ? sqrtf(s2) : 0.f;
                o.y = s*((cv.y - mn1)*rs1) + m;
                *(float2*)(out + ghi + ch) = o;
            }
        }
    }
}

// ---------------- launch ----------------
extern "C" void kernel_launch(void* const* d_in, const int* in_sizes, int n_in,
                              void* d_out, int out_size){
    const float* content = (const float*)d_in[0];
    const float* style   = (const float*)d_in[1];
    const float* Wq = (const float*)d_in[2];
    const float* bq = (const float*)d_in[3];
    const float* Wk = (const float*)d_in[4];
    const float* bk = (const float*)d_in[5];
    const float* Wv = (const float*)d_in[6];
    const float* bv = (const float*)d_in[7];
    float* out = (float*)d_out;

    cudaFuncSetAttribute(k_attn_mma, cudaFuncAttributeMaxDynamicSharedMemorySize, SMEM_ATT);

    k_stats_partial<<<dim3(NSPLIT, B_, 2), 256>>>(content, style);
    k_stats_final<<<dim3(B_, 2), 256>>>();
    k_wcvt<<<dim3(8, 8, 3), dim3(32, 8)>>>(Wq, Wk, Wv);
    k_qkv<<<dim3(M_/64, 3), 256>>>(content, style, bq, bk, bv);
    k_attn_mma<<<M_/64, 256, SMEM_ATT>>>(content, out);
}

// round 15
// speedup vs baseline: 1.0249x; 1.0249x over previous
#include <cuda_runtime.h>
#include <cuda_fp16.h>
#include <cstdint>

#define B_ 4
#define N_ 4096
#define C_ 256
#define NSPLIT 32
#define M_ (B_*N_)
#define L2E 1.4426950408889634f

// ---- attention smem layout (bytes) ----
#define QS_OFF   0          // 64x512 = 32768
#define KS_OFF   32768      // 2 x 32768
#define VTS_OFF  98304      // 2 x 32768
#define PS_OFF   163840     // 2 x 8192 (reused for Z exchange)
#define SMEM_ATT 180224

// ---- k_qkv smem layout (bytes) ----
#define QA_OFF   0          // 2 x 8192   (A chunk double buffer)
#define QW_OFF   16384      // 2 x 32768  (W chunk double buffer)
#define SMEM_QKV 81920

// ---------------- device scratch ----------------
__device__ float g_psum[2*B_*NSPLIT*C_];
__device__ float g_psq [2*B_*NSPLIT*C_];
__device__ float g_mean[2*B_*C_];
__device__ float g_rstd[2*B_*C_];
__device__ __half g_Wth[3*C_*C_];           // W^T fp16: [which][n][k]
__device__ __half g_Qh[M_*C_];              // l2norm'd, pre-scaled by log2(e)
__device__ __half g_Kh[M_*C_];              // l2norm'd
__device__ __half g_VTh[B_*C_*N_];          // [b][c][n]

typedef unsigned long long ull;

// ---------------- PTX helpers ----------------
__device__ __forceinline__ uint32_t s2u(const void* p){
    uint32_t a;
    asm("{ .reg .u64 t; cvta.to.shared.u64 t, %1; cvt.u32.u64 %0, t; }" : "=r"(a) : "l"(p));
    return a;
}
__device__ __forceinline__ void ldm4(uint32_t a, uint32_t& r0, uint32_t& r1,
                                     uint32_t& r2, uint32_t& r3){
    asm volatile("ldmatrix.sync.aligned.m8n8.x4.shared.b16 {%0,%1,%2,%3}, [%4];"
        : "=r"(r0), "=r"(r1), "=r"(r2), "=r"(r3) : "r"(a));
}
__device__ __forceinline__ void mma16816(float* d, uint32_t a0, uint32_t a1,
                                         uint32_t a2, uint32_t a3,
                                         uint32_t b0, uint32_t b1){
    asm volatile("mma.sync.aligned.m16n8k16.row.col.f32.f16.f16.f32 "
        "{%0,%1,%2,%3},{%4,%5,%6,%7},{%8,%9},{%0,%1,%2,%3};"
        : "+f"(d[0]), "+f"(d[1]), "+f"(d[2]), "+f"(d[3])
        : "r"(a0), "r"(a1), "r"(a2), "r"(a3), "r"(b0), "r"(b1));
}
// fp16-accumulator variant: D/C are 2 x f16x2 regs
__device__ __forceinline__ void mma16816h(uint32_t* d, uint32_t a0, uint32_t a1,
                                          uint32_t a2, uint32_t a3,
                                          uint32_t b0, uint32_t b1){
    asm volatile("mma.sync.aligned.m16n8k16.row.col.f16.f16.f16.f16 "
        "{%0,%1},{%2,%3,%4,%5},{%6,%7},{%0,%1};"
        : "+r"(d[0]), "+r"(d[1])
        : "r"(a0), "r"(a1), "r"(a2), "r"(a3), "r"(b0), "r"(b1));
}
__device__ __forceinline__ void cpa16(uint32_t s, const void* g){
    asm volatile("cp.async.cg.shared.global [%0], [%1], 16;" :: "r"(s), "l"(g));
}
#define CPCOMMIT() asm volatile("cp.async.commit_group;")
#define CPWAIT(n)  asm volatile("cp.async.wait_group %0;" :: "n"(n))

__device__ __forceinline__ uint32_t ex2h2(uint32_t h){
    uint32_t r; asm("ex2.approx.f16x2 %0, %1;" : "=r"(r) : "r"(h)); return r;
}
__device__ __forceinline__ uint32_t sqr2(uint32_t v){
    uint32_t r; asm("mul.rn.f16x2 %0, %1, %1;" : "=r"(r) : "r"(v)); return r;
}
__device__ __forceinline__ float hsum2(uint32_t h2){
    __half2 h = *(__half2*)&h2;
    float2 f = __half22float2(h);
    return f.x + f.y;
}

// ---------------- instance-norm statistics ----------------
__global__ void k_stats_partial(const float* __restrict__ content,
                                const float* __restrict__ style){
    const float* x = blockIdx.z ? style : content;
    const int b = blockIdx.y, sp = blockIdx.x, c = threadIdx.x;
    const int rows = N_ / NSPLIT;
    const float* base = x + (size_t)b*N_*C_ + (size_t)sp*rows*C_ + c;
    float s = 0.f, ss = 0.f;
    #pragma unroll 4
    for (int r = 0; r < rows; r++){
        float v = base[(size_t)r*C_];
        s += v; ss += v*v;
    }
    int idx = ((blockIdx.z*B_ + b)*NSPLIT + sp)*C_ + c;
    g_psum[idx] = s; g_psq[idx] = ss;
}

__global__ void k_stats_final(){
    const int b = blockIdx.x, t = blockIdx.y, c = threadIdx.x;
    float s = 0.f, ss = 0.f;
    #pragma unroll
    for (int sp = 0; sp < NSPLIT; sp++){
        int idx = ((t*B_ + b)*NSPLIT + sp)*C_ + c;
        s += g_psum[idx]; ss += g_psq[idx];
    }
    float mean = s * (1.f/N_);
    float var  = fmaxf(ss * (1.f/N_) - mean*mean, 0.f);
    g_mean[(t*B_ + b)*C_ + c] = mean;
    g_rstd[(t*B_ + b)*C_ + c] = rsqrtf(var + 1e-5f);
}

// ---------------- W transpose + fp16 convert ----------------
__global__ void k_wcvt(const float* __restrict__ Wq, const float* __restrict__ Wk,
                       const float* __restrict__ Wv){
    __shared__ float t[32][33];
    const float* W = (blockIdx.z == 0) ? Wq : (blockIdx.z == 1) ? Wk : Wv;
    __half* O = g_Wth + (size_t)blockIdx.z*C_*C_;
    const int k0 = blockIdx.x << 5, n0 = blockIdx.y << 5;
    for (int i = threadIdx.y; i < 32; i += 8)
        t[i][threadIdx.x] = W[(size_t)(k0 + i)*C_ + n0 + threadIdx.x];
    __syncthreads();
    for (int i = threadIdx.y; i < 32; i += 8)
        O[(size_t)(n0 + i)*C_ + k0 + threadIdx.x] = __float2half_rn(t[threadIdx.x][i]);
}

// ---------------- fused norm + 1x1 conv (fp16 HMMA), pipelined ---------------
// grid (M_/64, 3): which = 0 Q (l2norm*log2e), 1 K (l2norm), 2 V (transpose)
__global__ __launch_bounds__(256, 2) void k_qkv(const float* __restrict__ content,
                                                const float* __restrict__ style,
                                                const float* __restrict__ bq,
                                                const float* __restrict__ bk,
                                                const float* __restrict__ bv){
    __shared__ __align__(16) char smem[SMEM_QKV];
    const uint32_t sb = s2u(smem);
    const int tid = threadIdx.x, warp = tid >> 5, lane = tid & 31;
    const int wq2 = warp >> 2, wc4 = warp & 3;
    const int mi = lane >> 3, r8 = lane & 7, l4 = lane >> 2, l2 = lane & 3;
    const int which = blockIdx.y;
    const int tm = blockIdx.x << 6;
    const int b = tm >> 12;
    const float* A = (which == 0) ? content : style;
    const float* bias = (which == 0) ? bq : (which == 1) ? bk : bv;
    const __half* wsrc = g_Wth + (size_t)which*C_*C_;
    const float* meanp = g_mean + (which == 1 ? B_*C_ : 0) + b*C_;
    const float* rstdp = g_rstd + (which == 1 ? B_*C_ : 0) + b*C_;
    const bool donorm = which < 2;

    const int ar0 = tid >> 4;            // base row (+16*i)
    const int ac4 = tid & 15;            // channel quad within chunk

    float acc[2][8][4];
    #pragma unroll
    for (int mt = 0; mt < 2; mt++)
        #pragma unroll
        for (int ct = 0; ct < 8; ct++){
            acc[mt][ct][0] = 0.f; acc[mt][ct][1] = 0.f;
            acc[mt][ct][2] = 0.f; acc[mt][ct][3] = 0.f;
        }

    // prologue: W(0) cp.async, A(0) -> regs
    for (int it = tid; it < 2048; it += 256){
        int n = it >> 3, c16 = it & 7;
        cpa16(sb + QW_OFF + n*128 + (((uint32_t)(c16 ^ (n & 7))) << 4),
              wsrc + (size_t)n*C_ + (c16 << 3));
    }
    CPCOMMIT();
    float4 av[4];
    #pragma unroll
    for (int i = 0; i < 4; i++)
        av[i] = *(const float4*)(A + (size_t)(tm + ar0 + (i << 4))*C_ + (ac4 << 2));

    for (int kc = 0; kc < 4; kc++){
        __syncthreads();
        {
            const int cc = (kc << 6) + (ac4 << 2);
            float4 mn, rs;
            if (donorm){ mn = *(const float4*)(meanp + cc); rs = *(const float4*)(rstdp + cc); }
            char* ab = smem + QA_OFF + (kc & 1)*8192;
            #pragma unroll
            for (int i = 0; i < 4; i++){
                float4 v = av[i];
                if (donorm){
                    v.x = (v.x - mn.x)*rs.x; v.y = (v.y - mn.y)*rs.y;
                    v.z = (v.z - mn.z)*rs.z; v.w = (v.w - mn.w)*rs.w;
                }
                __half2 h0 = __floats2half2_rn(v.x, v.y);
                __half2 h1 = __floats2half2_rn(v.z, v.w);
                uint2 u; u.x = *(uint32_t*)&h0; u.y = *(uint32_t*)&h1;
                int r = ar0 + (i << 4);
                int c16 = ac4 >> 1, sub = ac4 & 1;
                *(uint2*)(ab + (r << 7) + ((c16 ^ (r & 7)) << 4) + (sub << 3)) = u;
            }
        }
        if (kc < 3){
            for (int it = tid; it < 2048; it += 256){
                int n = it >> 3, c16 = it & 7;
                cpa16(sb + QW_OFF + ((kc + 1) & 1)*32768 + n*128 + (((uint32_t)(c16 ^ (n & 7))) << 4),
                      wsrc + (size_t)n*C_ + ((kc + 1) << 6) + (c16 << 3));
            }
            CPCOMMIT();
            #pragma unroll
            for (int i = 0; i < 4; i++)
                av[i] = *(const float4*)(A + (size_t)(tm + ar0 + (i << 4))*C_ + ((kc + 1) << 6) + (ac4 << 2));
            CPWAIT(1);
        } else {
            CPWAIT(0);
        }
        __syncthreads();

        const uint32_t abase = sb + QA_OFF + (kc & 1)*8192;
        const uint32_t wbase = sb + QW_OFF + (kc & 1)*32768;
        #pragma unroll
        for (int cs = 0; cs < 4; cs++){
            uint32_t colA = ((uint32_t)((2*cs + (mi >> 1)) ^ r8)) << 4;
            uint32_t a00,a01,a02,a03, a10,a11,a12,a13;
            uint32_t aAb = abase + (uint32_t)((wq2 << 5) + r8 + ((mi & 1) << 3))*128;
            ldm4(aAb + colA, a00,a01,a02,a03);
            ldm4(aAb + 16*128 + colA, a10,a11,a12,a13);
            uint32_t colB = ((uint32_t)((2*cs + (mi & 1)) ^ r8)) << 4;
            #pragma unroll
            for (int ctp = 0; ctp < 4; ctp++){
                uint32_t w0,w1,w2,w3;
                ldm4(wbase + (uint32_t)((wc4 << 6) + (ctp << 4) + r8 + ((mi >> 1) << 3))*128 + colB,
                     w0,w1,w2,w3);
                mma16816(acc[0][2*ctp],   a00,a01,a02,a03, w0,w1);
                mma16816(acc[0][2*ctp+1], a00,a01,a02,a03, w2,w3);
                mma16816(acc[1][2*ctp],   a10,a11,a12,a13, w0,w1);
                mma16816(acc[1][2*ctp+1], a10,a11,a12,a13, w2,w3);
            }
        }
    }
    __syncthreads();

    float ssq[2][2] = {{0.f,0.f},{0.f,0.f}};
    #pragma unroll
    for (int mt = 0; mt < 2; mt++)
        #pragma unroll
        for (int ct = 0; ct < 8; ct++){
            int ch = (wc4 << 6) + (ct << 3) + (l2 << 1);
            float2 bb = *(const float2*)(bias + ch);
            acc[mt][ct][0] += bb.x; acc[mt][ct][1] += bb.y;
            acc[mt][ct][2] += bb.x; acc[mt][ct][3] += bb.y;
            if (which < 2){
                ssq[mt][0] += acc[mt][ct][0]*acc[mt][ct][0] + acc[mt][ct][1]*acc[mt][ct][1];
                ssq[mt][1] += acc[mt][ct][2]*acc[mt][ct][2] + acc[mt][ct][3]*acc[mt][ct][3];
            }
        }

    if (which < 2){
        #pragma unroll
        for (int mt = 0; mt < 2; mt++)
            #pragma unroll
            for (int h = 0; h < 2; h++){
                float v = ssq[mt][h];
                v += __shfl_xor_sync(0xffffffffu, v, 1);
                v += __shfl_xor_sync(0xffffffffu, v, 2);
                ssq[mt][h] = v;
            }
        float* ssm = (float*)smem;    // [4][64]
        if (l2 == 0){
            #pragma unroll
            for (int mt = 0; mt < 2; mt++){
                int rl = (wq2 << 5) + (mt << 4) + l4;
                ssm[wc4*64 + rl]     = ssq[mt][0];
                ssm[wc4*64 + rl + 8] = ssq[mt][1];
            }
        }
        __syncthreads();
        const float qsc = (which == 0) ? L2E : 1.f;
        __half* O = (which == 0) ? g_Qh : g_Kh;
        #pragma unroll
        for (int mt = 0; mt < 2; mt++){
            int rl = (wq2 << 5) + (mt << 4) + l4;
            float scl = rsqrtf(ssm[rl] + ssm[64+rl] + ssm[128+rl] + ssm[192+rl] + 1e-12f) * qsc;
            int rh = rl + 8;
            float sch = rsqrtf(ssm[rh] + ssm[64+rh] + ssm[128+rh] + ssm[192+rh] + 1e-12f) * qsc;
            #pragma unroll
            for (int ct = 0; ct < 8; ct++){
                int ch = (wc4 << 6) + (ct << 3) + (l2 << 1);
                __half2 h = __floats2half2_rn(acc[mt][ct][0]*scl, acc[mt][ct][1]*scl);
                *(uint32_t*)(O + (size_t)(tm + rl)*C_ + ch) = *(uint32_t*)&h;
                h = __floats2half2_rn(acc[mt][ct][2]*sch, acc[mt][ct][3]*sch);
                *(uint32_t*)(O + (size_t)(tm + rh)*C_ + ch) = *(uint32_t*)&h;
            }
        }
    } else {
        __half* T = (__half*)smem;    // [64][264]
        #pragma unroll
        for (int mt = 0; mt < 2; mt++){
            int rl = (wq2 << 5) + (mt << 4) + l4, rh = rl + 8;
            #pragma unroll
            for (int ct = 0; ct < 8; ct++){
                int ch = (wc4 << 6) + (ct << 3) + (l2 << 1);
                __half2 h = __floats2half2_rn(acc[mt][ct][0], acc[mt][ct][1]);
                *(uint32_t*)&T[rl*264 + ch] = *(uint32_t*)&h;
                h = __floats2half2_rn(acc[mt][ct][2], acc[mt][ct][3]);
                *(uint32_t*)&T[rh*264 + ch] = *(uint32_t*)&h;
            }
        }
        __syncthreads();
        const int c = tid;
        const int n0 = tm & (N_ - 1);
        __half* Ov = g_VTh + ((size_t)(b*C_ + c))*N_ + n0;
        #pragma unroll
        for (int j = 0; j < 8; j++){
            __half hh[8];
            #pragma unroll
            for (int i = 0; i < 8; i++) hh[i] = T[(j*8 + i)*264 + c];
            *(uint4*)(Ov + j*8) = *(uint4*)hh;
        }
    }
}

// ---------------- HMMA fused attention + AdaIN ----------------
// R12 config (Q hoist + fp16-accum phase A) + fp16-accum accM (reg relief).
// CTA = 64 queries x 256 channels x all 4096 keys. 256 threads (8 warps).
__global__ __launch_bounds__(256, 1) void k_attn_mma(const float* __restrict__ content,
                                                     float* __restrict__ out){
    extern __shared__ char sm[];
    const uint32_t sb = s2u(sm);
    const int tid = threadIdx.x, warp = tid >> 5, lane = tid & 31;
    const int q0 = blockIdx.x << 6;
    const int b  = q0 >> 12;
    const int wq = warp & 3, wk2 = warp >> 2;        // phase A tiling (16q x 32k)
    const int wq2 = warp >> 2, wc4 = warp & 3;       // phase B tiling (32q x 64ch)
    const int mi = lane >> 3, r8 = lane & 7;
    const int l4 = lane >> 2, l2 = lane & 3;

    const __half* vt_base = g_VTh + (size_t)b*C_*N_;
    const uint32_t aA     = sb + QS_OFF + (uint32_t)((wq << 4) + r8 + ((mi & 1) << 3))*512;
    const uint32_t aB_off = (uint32_t)((wk2 << 5) + r8 + ((mi >> 1) << 3))*512;
    const uint32_t pB_off = (uint32_t)((wq2 << 5) + r8 + ((mi & 1) << 3))*128;
    const uint32_t vB_off = (uint32_t)((wc4 << 6) + r8 + ((mi >> 1) << 3))*128;

    uint32_t accMh[2][8][2];                 // fp16x2 accum: Σ p*v
    float accV2[2][8][4];                    // fp32 accum: Σ p*v^2
    #pragma unroll
    for (int mt = 0; mt < 2; mt++)
        #pragma unroll
        for (int ct = 0; ct < 8; ct++){
            accMh[mt][ct][0] = 0u; accMh[mt][ct][1] = 0u;
            #pragma unroll
            for (int j = 0; j < 4; j++) accV2[mt][ct][j] = 0.f;
        }
    float z0 = 0.f, z1 = 0.f;

    auto loadK = [&](int kt, int buf){
        uint32_t kdst = sb + KS_OFF + buf*32768;
        for (int it = tid; it < 2048; it += 256){
            int r = it >> 5, c16 = it & 31;
            cpa16(kdst + r*512 + (((uint32_t)(c16 ^ (r & 7))) << 4),
                  g_Kh + (((size_t)((b << 12) + (kt << 6) + r)) << 8) + (c16 << 3));
        }
    };
    auto loadVT = [&](int kt, int buf){
        uint32_t vdst = sb + VTS_OFF + buf*32768;
        for (int it = tid; it < 2048; it += 256){
            int r = it >> 3, c16 = it & 7;
            cpa16(vdst + r*128 + (((uint32_t)(c16 ^ (r & 7))) << 4),
                  vt_base + (((size_t)r) << 12) + (kt << 6) + (c16 << 3));
        }
    };
    // fp16 logits dd[nt][0]=rows r, dd[nt][1]=rows r+8 -> exp -> P store
    auto expStore = [&](uint32_t dd[4][2], int j){
        char* pb = sm + PS_OFF + (j & 1)*8192;
        const int qlo = (wq << 4) + l4;
        #pragma unroll
        for (int nt = 0; nt < 4; nt++){
            uint32_t plo = ex2h2(dd[nt][0]);
            uint32_t phi = ex2h2(dd[nt][1]);
            z0 += hsum2(plo);
            z1 += hsum2(phi);
            int c16p = (wk2 << 2) + nt;
            uint32_t sw = ((uint32_t)(c16p ^ l4)) << 4;
            *(uint32_t*)(pb + qlo*128 + sw + (l2 << 2))       = plo;
            *(uint32_t*)(pb + (qlo + 8)*128 + sw + (l2 << 2)) = phi;
        }
    };
    auto phaseBs = [&](uint32_t aPb, uint32_t aVb, int s){
        uint32_t colA = ((uint32_t)((2*s + (mi >> 1)) ^ r8)) << 4;
        uint32_t p00,p01,p02,p03, p10,p11,p12,p13;
        ldm4(aPb + colA, p00,p01,p02,p03);
        ldm4(aPb + 16*128 + colA, p10,p11,p12,p13);
        uint32_t colB = ((uint32_t)((2*s + (mi & 1)) ^ r8)) << 4;
        #pragma unroll
        for (int ctp = 0; ctp < 4; ctp++){
            uint32_t v0,v1,v2,v3;
            ldm4(aVb + (uint32_t)(ctp << 4)*128 + colB, v0,v1,v2,v3);
            mma16816h(accMh[0][2*ctp],   p00,p01,p02,p03, v0,v1);
            mma16816h(accMh[0][2*ctp+1], p00,p01,p02,p03, v2,v3);
            mma16816h(accMh[1][2*ctp],   p10,p11,p12,p13, v0,v1);
            mma16816h(accMh[1][2*ctp+1], p10,p11,p12,p13, v2,v3);
            uint32_t w0 = sqr2(v0), w1 = sqr2(v1), w2 = sqr2(v2), w3 = sqr2(v3);
            mma16816(accV2[0][2*ctp],   p00,p01,p02,p03, w0,w1);
            mma16816(accV2[0][2*ctp+1], p00,p01,p02,p03, w2,w3);
            mma16816(accV2[1][2*ctp],   p10,p11,p12,p13, w0,w1);
            mma16816(accV2[1][2*ctp+1], p10,p11,p12,p13, w2,w3);
        }
    };

    // ---- prologue ----
    for (int it = tid; it < 2048; it += 256){
        int r = it >> 5, c16 = it & 31;
        cpa16(sb + QS_OFF + r*512 + (((uint32_t)(c16 ^ (r & 7))) << 4),
              g_Qh + (((size_t)(q0 + r)) << 8) + (c16 << 3));
    }
    loadK(0, 0);
    CPCOMMIT();                 // G0: Q + K(0)
    loadVT(0, 0);
    loadK(1, 1);
    CPCOMMIT();                 // G1: VT(0) + K(1)
    CPWAIT(1);                  // G0 complete
    __syncthreads();

    // hoist Q fragments (live across all tiles)
    uint32_t qf[16][4];
    #pragma unroll
    for (int cs = 0; cs < 16; cs++)
        ldm4(aA + (((uint32_t)((2*cs + (mi >> 1)) ^ r8)) << 4),
             qf[cs][0], qf[cs][1], qf[cs][2], qf[cs][3]);

    {   // phase A(0) -> P[0]  (fp16 accumulation)
        const uint32_t kb0 = sb + KS_OFF + aB_off;
        uint32_t dd[4][2];
        #pragma unroll
        for (int i = 0; i < 4; i++){ dd[i][0] = 0u; dd[i][1] = 0u; }
        #pragma unroll
        for (int cs = 0; cs < 16; cs++){
            uint32_t b0,b1,b2,b3;
            uint32_t cB = ((uint32_t)((2*cs + (mi & 1)) ^ r8)) << 4;
            ldm4(kb0 + cB, b0,b1,b2,b3);
            mma16816h(dd[0], qf[cs][0], qf[cs][1], qf[cs][2], qf[cs][3], b0,b1);
            mma16816h(dd[1], qf[cs][0], qf[cs][1], qf[cs][2], qf[cs][3], b2,b3);
            ldm4(kb0 + 16*512 + cB, b0,b1,b2,b3);
            mma16816h(dd[2], qf[cs][0], qf[cs][1], qf[cs][2], qf[cs][3], b0,b1);
            mma16816h(dd[3], qf[cs][0], qf[cs][1], qf[cs][2], qf[cs][3], b2,b3);
        }
        expStore(dd, 0);
    }

    // ---- main loop: 63 fused iterations, A(i+1) interleaved with B(i) ----
    for (int i = 0; i < 63; i++){
        CPWAIT(0);              // K(i+1), VT(i) complete
        __syncthreads();        // load visibility + P(i) stores + buffer reuse
        if (i < 62) loadK(i + 2, i & 1);
        loadVT(i + 1, (i + 1) & 1);
        CPCOMMIT();

        const uint32_t kb0 = sb + KS_OFF + ((i + 1) & 1)*32768 + aB_off;
        const uint32_t aPb = sb + PS_OFF  + (i & 1)*8192  + pB_off;
        const uint32_t aVb = sb + VTS_OFF + (i & 1)*32768 + vB_off;
        uint32_t dd[4][2];
        #pragma unroll
        for (int k = 0; k < 4; k++){ dd[k][0] = 0u; dd[k][1] = 0u; }

        #pragma unroll
        for (int s = 0; s < 4; s++){
            // -- A chunk: k-steps 4s..4s+3 on K[(i+1)&1] (Q frags in regs) --
            #pragma unroll
            for (int c = 0; c < 4; c++){
                const int cs = 4*s + c;
                uint32_t b0,b1,b2,b3;
                uint32_t cB = ((uint32_t)((2*cs + (mi & 1)) ^ r8)) << 4;
                ldm4(kb0 + cB, b0,b1,b2,b3);
                mma16816h(dd[0], qf[cs][0], qf[cs][1], qf[cs][2], qf[cs][3], b0,b1);
                mma16816h(dd[1], qf[cs][0], qf[cs][1], qf[cs][2], qf[cs][3], b2,b3);
                ldm4(kb0 + 16*512 + cB, b0,b1,b2,b3);
                mma16816h(dd[2], qf[cs][0], qf[cs][1], qf[cs][2], qf[cs][3], b0,b1);
                mma16816h(dd[3], qf[cs][0], qf[cs][1], qf[cs][2], qf[cs][3], b2,b3);
            }
            // -- B chunk s: P[i&1] x VT[i&1] (independent stream) --
            phaseBs(aPb, aVb, s);
        }
        expStore(dd, i + 1);    // P[(i+1)&1]
    }

    // ---- final tile: B(63) only ----
    CPWAIT(0);
    __syncthreads();
    {
        const uint32_t aPb = sb + PS_OFF  + (63 & 1)*8192  + pB_off;
        const uint32_t aVb = sb + VTS_OFF + (63 & 1)*32768 + vB_off;
        #pragma unroll
        for (int s = 0; s < 4; s++) phaseBs(aPb, aVb, s);
    }
    __syncthreads();            // P buffers free for Z exchange

    // ---- Z exchange: reduce over l2 lanes, then across wk2 via smem ----
    z0 += __shfl_xor_sync(0xffffffffu, z0, 1);
    z0 += __shfl_xor_sync(0xffffffffu, z0, 2);
    z1 += __shfl_xor_sync(0xffffffffu, z1, 1);
    z1 += __shfl_xor_sync(0xffffffffu, z1, 2);
    float* Zs = (float*)(sm + PS_OFF);      // [64][2]
    if (l2 == 0){
        Zs[(((wq << 4) + l4) << 1) + wk2]     = z0;
        Zs[(((wq << 4) + l4 + 8) << 1) + wk2] = z1;
    }
    __syncthreads();

    // ---- epilogue: M/S2, AdaIN, store ----
    const float* meanp = g_mean + b*C_;
    const float* rstdp = g_rstd + b*C_;
    #pragma unroll
    for (int mt = 0; mt < 2; mt++){
        const int rloc = (wq2 << 5) + (mt << 4) + l4;
        const float izlo = 1.f / (Zs[rloc << 1] + Zs[(rloc << 1) + 1]);
        const float izhi = 1.f / (Zs[(rloc + 8) << 1] + Zs[((rloc + 8) << 1) + 1]);
        const int rl = q0 + rloc;
        const size_t glo = ((size_t)rl) << 8;
        const size_t ghi = ((size_t)(rl + 8)) << 8;
        #pragma unroll
        for (int ct = 0; ct < 8; ct++){
            const int ch = (wc4 << 6) + (ct << 3) + (l2 << 1);
            const float mn0 = meanp[ch], mn1 = meanp[ch+1];
            const float rs0 = rstdp[ch], rs1 = rstdp[ch+1];
            float2 mlo = __half22float2(*(__half2*)&accMh[mt][ct][0]);
            float2 mhi = __half22float2(*(__half2*)&accMh[mt][ct][1]);
            {
                float2 cv = *(const float2*)(content + glo + ch);
                float m = mlo.x*izlo;
                float s2 = accV2[mt][ct][0]*izlo - m*m;
                float s = s2 > 0.f ? sqrtf(s2) : 0.f;
                float2 o;
                o.x = s*((cv.x - mn0)*rs0) + m;
                m = mlo.y*izlo;
                s2 = accV2[mt][ct][1]*izlo - m*m;
                s = s2 > 0.f ? sqrtf(s2) : 0.f;
                o.y = s*((cv.y - mn1)*rs1) + m;
                *(float2*)(out + glo + ch) = o;
            }
            {
                float2 cv = *(const float2*)(content + ghi + ch);
                float m = mhi.x*izhi;
                float s2 = accV2[mt][ct][2]*izhi - m*m;
                float s = s2 > 0.f ? sqrtf(s2) : 0.f;
                float2 o;
                o.x = s*((cv.x - mn0)*rs0) + m;
                m = mhi.y*izhi;
                s2 = accV2[mt][ct][3]*izhi - m*m;
                s = s2 > 0.f ? sqrtf(s2) : 0.f;
                o.y = s*((cv.y - mn1)*rs1) + m;
                *(float2*)(out + ghi + ch) = o;
            }
        }
    }
}

// ---------------- launch ----------------
extern "C" void kernel_launch(void* const* d_in, const int* in_sizes, int n_in,
                              void* d_out, int out_size){
    const float* content = (const float*)d_in[0];
    const float* style   = (const float*)d_in[1];
    const float* Wq = (const float*)d_in[2];
    const float* bq = (const float*)d_in[3];
    const float* Wk = (const float*)d_in[4];
    const float* bk = (const float*)d_in[5];
    const float* Wv = (const float*)d_in[6];
    const float* bv = (const float*)d_in[7];
    float* out = (float*)d_out;

    cudaFuncSetAttribute(k_attn_mma, cudaFuncAttributeMaxDynamicSharedMemorySize, SMEM_ATT);

    k_stats_partial<<<dim3(NSPLIT, B_, 2), 256>>>(content, style);
    k_stats_final<<<dim3(B_, 2), 256>>>();
    k_wcvt<<<dim3(8, 8, 3), dim3(32, 8)>>>(Wq, Wk, Wv);
    k_qkv<<<dim3(M_/64, 3), 256>>>(content, style, bq, bk, bv);
    k_attn_mma<<<M_/64, 256, SMEM_ATT>>>(content, out);
}

// round 16
// speedup vs baseline: 1.0608x; 1.0350x over previous
#include <cuda_runtime.h>
#include <cuda_fp16.h>
#include <cstdint>

#define B_ 4
#define N_ 4096
#define C_ 256
#define NSPLIT 32
#define M_ (B_*N_)
#define L2E 1.4426950408889634f

// ---- attention smem layout (bytes) ----
#define QS_OFF   0          // 64x512 = 32768
#define KS_OFF   32768      // 2 x 32768
#define VTS_OFF  98304      // 2 x 32768
#define PS_OFF   163840     // 2 x 8192 (reused for Z exchange)
#define SMEM_ATT 180224

// ---- k_qkv smem layout (bytes) ----
#define QA_OFF   0          // 2 x 8192   (A chunk double buffer)
#define QW_OFF   16384      // 2 x 32768  (W chunk double buffer)
#define SMEM_QKV 81920

// ---------------- device scratch ----------------
__device__ float g_psum[2*B_*NSPLIT*C_];
__device__ float g_psq [2*B_*NSPLIT*C_];
__device__ float g_mean[2*B_*C_];
__device__ float g_rstd[2*B_*C_];
__device__ __half g_Wth[3*C_*C_];           // W^T fp16: [which][n][k]
__device__ __half g_Qh[M_*C_];              // l2norm'd, pre-scaled by log2(e)
__device__ __half g_Kh[M_*C_];              // l2norm'd
__device__ __half g_VTh[B_*C_*N_];          // [b][c][n]

typedef unsigned long long ull;

// ---------------- PTX helpers ----------------
__device__ __forceinline__ uint32_t s2u(const void* p){
    uint32_t a;
    asm("{ .reg .u64 t; cvta.to.shared.u64 t, %1; cvt.u32.u64 %0, t; }" : "=r"(a) : "l"(p));
    return a;
}
__device__ __forceinline__ void ldm4(uint32_t a, uint32_t& r0, uint32_t& r1,
                                     uint32_t& r2, uint32_t& r3){
    asm volatile("ldmatrix.sync.aligned.m8n8.x4.shared.b16 {%0,%1,%2,%3}, [%4];"
        : "=r"(r0), "=r"(r1), "=r"(r2), "=r"(r3) : "r"(a));
}
__device__ __forceinline__ void mma16816(float* d, uint32_t a0, uint32_t a1,
                                         uint32_t a2, uint32_t a3,
                                         uint32_t b0, uint32_t b1){
    asm volatile("mma.sync.aligned.m16n8k16.row.col.f32.f16.f16.f32 "
        "{%0,%1,%2,%3},{%4,%5,%6,%7},{%8,%9},{%0,%1,%2,%3};"
        : "+f"(d[0]), "+f"(d[1]), "+f"(d[2]), "+f"(d[3])
        : "r"(a0), "r"(a1), "r"(a2), "r"(a3), "r"(b0), "r"(b1));
}
// fp16-accumulator variant: D/C are 2 x f16x2 regs
__device__ __forceinline__ void mma16816h(uint32_t* d, uint32_t a0, uint32_t a1,
                                          uint32_t a2, uint32_t a3,
                                          uint32_t b0, uint32_t b1){
    asm volatile("mma.sync.aligned.m16n8k16.row.col.f16.f16.f16.f16 "
        "{%0,%1},{%2,%3,%4,%5},{%6,%7},{%0,%1};"
        : "+r"(d[0]), "+r"(d[1])
        : "r"(a0), "r"(a1), "r"(a2), "r"(a3), "r"(b0), "r"(b1));
}
__device__ __forceinline__ void cpa16(uint32_t s, const void* g){
    asm volatile("cp.async.cg.shared.global [%0], [%1], 16;" :: "r"(s), "l"(g));
}
#define CPCOMMIT() asm volatile("cp.async.commit_group;")
#define CPWAIT(n)  asm volatile("cp.async.wait_group %0;" :: "n"(n))

__device__ __forceinline__ uint32_t ex2h2(uint32_t h){
    uint32_t r; asm("ex2.approx.f16x2 %0, %1;" : "=r"(r) : "r"(h)); return r;
}
__device__ __forceinline__ uint32_t sqr2(uint32_t v){
    uint32_t r; asm("mul.rn.f16x2 %0, %1, %1;" : "=r"(r) : "r"(v)); return r;
}
__device__ __forceinline__ float hsum2(uint32_t h2){
    __half2 h = *(__half2*)&h2;
    float2 f = __half22float2(h);
    return f.x + f.y;
}

// ---------------- instance-norm statistics (vectorized) ----------------
// grid (NSPLIT, B_, 2), 256 thr. thread = (channel quad cq, row group rg).
// Each thread: 32 float4 loads (stride 4 rows), smem-reduce over 4 rgs.
__global__ void k_stats_partial(const float* __restrict__ content,
                                const float* __restrict__ style){
    __shared__ float4 smS[3][64];
    __shared__ float4 smQ[3][64];
    const float* x = blockIdx.z ? style : content;
    const int b = blockIdx.y, sp = blockIdx.x;
    const int cq = threadIdx.x & 63, rg = threadIdx.x >> 6;
    const float* base = x + ((size_t)b*N_ + sp*(N_/NSPLIT) + rg)*C_ + (cq << 2);
    float4 s = {0.f,0.f,0.f,0.f}, q = {0.f,0.f,0.f,0.f};
    #pragma unroll 8
    for (int i = 0; i < 32; i++){
        float4 v = *(const float4*)(base + (size_t)i*4*C_);
        s.x += v.x; s.y += v.y; s.z += v.z; s.w += v.w;
        q.x += v.x*v.x; q.y += v.y*v.y; q.z += v.z*v.z; q.w += v.w*v.w;
    }
    if (rg){ smS[rg-1][cq] = s; smQ[rg-1][cq] = q; }
    __syncthreads();
    if (rg == 0){
        #pragma unroll
        for (int j = 0; j < 3; j++){
            float4 a = smS[j][cq], c = smQ[j][cq];
            s.x += a.x; s.y += a.y; s.z += a.z; s.w += a.w;
            q.x += c.x; q.y += c.y; q.z += c.z; q.w += c.w;
        }
        int idx = ((blockIdx.z*B_ + b)*NSPLIT + sp)*C_ + (cq << 2);
        *(float4*)(g_psum + idx) = s;
        *(float4*)(g_psq  + idx) = q;
    }
}

__global__ void k_stats_final(){
    const int b = blockIdx.x, t = blockIdx.y, c = threadIdx.x;
    float s = 0.f, ss = 0.f;
    #pragma unroll
    for (int sp = 0; sp < NSPLIT; sp++){
        int idx = ((t*B_ + b)*NSPLIT + sp)*C_ + c;
        s += g_psum[idx]; ss += g_psq[idx];
    }
    float mean = s * (1.f/N_);
    float var  = fmaxf(ss * (1.f/N_) - mean*mean, 0.f);
    g_mean[(t*B_ + b)*C_ + c] = mean;
    g_rstd[(t*B_ + b)*C_ + c] = rsqrtf(var + 1e-5f);
}

// ---------------- W transpose + fp16 convert ----------------
__global__ void k_wcvt(const float* __restrict__ Wq, const float* __restrict__ Wk,
                       const float* __restrict__ Wv){
    __shared__ float t[32][33];
    const float* W = (blockIdx.z == 0) ? Wq : (blockIdx.z == 1) ? Wk : Wv;
    __half* O = g_Wth + (size_t)blockIdx.z*C_*C_;
    const int k0 = blockIdx.x << 5, n0 = blockIdx.y << 5;
    for (int i = threadIdx.y; i < 32; i += 8)
        t[i][threadIdx.x] = W[(size_t)(k0 + i)*C_ + n0 + threadIdx.x];
    __syncthreads();
    for (int i = threadIdx.y; i < 32; i += 8)
        O[(size_t)(n0 + i)*C_ + k0 + threadIdx.x] = __float2half_rn(t[threadIdx.x][i]);
}

// ---------------- fused norm + 1x1 conv (fp16 HMMA), pipelined ---------------
// grid (M_/64, 3): which = 0 Q (l2norm*log2e), 1 K (l2norm), 2 V (transpose)
__global__ __launch_bounds__(256, 2) void k_qkv(const float* __restrict__ content,
                                                const float* __restrict__ style,
                                                const float* __restrict__ bq,
                                                const float* __restrict__ bk,
                                                const float* __restrict__ bv){
    __shared__ __align__(16) char smem[SMEM_QKV];
    const uint32_t sb = s2u(smem);
    const int tid = threadIdx.x, warp = tid >> 5, lane = tid & 31;
    const int wq2 = warp >> 2, wc4 = warp & 3;
    const int mi = lane >> 3, r8 = lane & 7, l4 = lane >> 2, l2 = lane & 3;
    const int which = blockIdx.y;
    const int tm = blockIdx.x << 6;
    const int b = tm >> 12;
    const float* A = (which == 0) ? content : style;
    const float* bias = (which == 0) ? bq : (which == 1) ? bk : bv;
    const __half* wsrc = g_Wth + (size_t)which*C_*C_;
    const float* meanp = g_mean + (which == 1 ? B_*C_ : 0) + b*C_;
    const float* rstdp = g_rstd + (which == 1 ? B_*C_ : 0) + b*C_;
    const bool donorm = which < 2;

    const int ar0 = tid >> 4;            // base row (+16*i)
    const int ac4 = tid & 15;            // channel quad within chunk

    float acc[2][8][4];
    #pragma unroll
    for (int mt = 0; mt < 2; mt++)
        #pragma unroll
        for (int ct = 0; ct < 8; ct++){
            acc[mt][ct][0] = 0.f; acc[mt][ct][1] = 0.f;
            acc[mt][ct][2] = 0.f; acc[mt][ct][3] = 0.f;
        }

    // prologue: W(0) cp.async, A(0) -> regs
    for (int it = tid; it < 2048; it += 256){
        int n = it >> 3, c16 = it & 7;
        cpa16(sb + QW_OFF + n*128 + (((uint32_t)(c16 ^ (n & 7))) << 4),
              wsrc + (size_t)n*C_ + (c16 << 3));
    }
    CPCOMMIT();
    float4 av[4];
    #pragma unroll
    for (int i = 0; i < 4; i++)
        av[i] = *(const float4*)(A + (size_t)(tm + ar0 + (i << 4))*C_ + (ac4 << 2));

    for (int kc = 0; kc < 4; kc++){
        __syncthreads();
        {
            const int cc = (kc << 6) + (ac4 << 2);
            float4 mn, rs;
            if (donorm){ mn = *(const float4*)(meanp + cc); rs = *(const float4*)(rstdp + cc); }
            char* ab = smem + QA_OFF + (kc & 1)*8192;
            #pragma unroll
            for (int i = 0; i < 4; i++){
                float4 v = av[i];
                if (donorm){
                    v.x = (v.x - mn.x)*rs.x; v.y = (v.y - mn.y)*rs.y;
                    v.z = (v.z - mn.z)*rs.z; v.w = (v.w - mn.w)*rs.w;
                }
                __half2 h0 = __floats2half2_rn(v.x, v.y);
                __half2 h1 = __floats2half2_rn(v.z, v.w);
                uint2 u; u.x = *(uint32_t*)&h0; u.y = *(uint32_t*)&h1;
                int r = ar0 + (i << 4);
                int c16 = ac4 >> 1, sub = ac4 & 1;
                *(uint2*)(ab + (r << 7) + ((c16 ^ (r & 7)) << 4) + (sub << 3)) = u;
            }
        }
        if (kc < 3){
            for (int it = tid; it < 2048; it += 256){
                int n = it >> 3, c16 = it & 7;
                cpa16(sb + QW_OFF + ((kc + 1) & 1)*32768 + n*128 + (((uint32_t)(c16 ^ (n & 7))) << 4),
                      wsrc + (size_t)n*C_ + ((kc + 1) << 6) + (c16 << 3));
            }
            CPCOMMIT();
            #pragma unroll
            for (int i = 0; i < 4; i++)
                av[i] = *(const float4*)(A + (size_t)(tm + ar0 + (i << 4))*C_ + ((kc + 1) << 6) + (ac4 << 2));
            CPWAIT(1);
        } else {
            CPWAIT(0);
        }
        __syncthreads();

        const uint32_t abase = sb + QA_OFF + (kc & 1)*8192;
        const uint32_t wbase = sb + QW_OFF + (kc & 1)*32768;
        #pragma unroll
        for (int cs = 0; cs < 4; cs++){
            uint32_t colA = ((uint32_t)((2*cs + (mi >> 1)) ^ r8)) << 4;
            uint32_t a00,a01,a02,a03, a10,a11,a12,a13;
            uint32_t aAb = abase + (uint32_t)((wq2 << 5) + r8 + ((mi & 1) << 3))*128;
            ldm4(aAb + colA, a00,a01,a02,a03);
            ldm4(aAb + 16*128 + colA, a10,a11,a12,a13);
            uint32_t colB = ((uint32_t)((2*cs + (mi & 1)) ^ r8)) << 4;
            #pragma unroll
            for (int ctp = 0; ctp < 4; ctp++){
                uint32_t w0,w1,w2,w3;
                ldm4(wbase + (uint32_t)((wc4 << 6) + (ctp << 4) + r8 + ((mi >> 1) << 3))*128 + colB,
                     w0,w1,w2,w3);
                mma16816(acc[0][2*ctp],   a00,a01,a02,a03, w0,w1);
                mma16816(acc[0][2*ctp+1], a00,a01,a02,a03, w2,w3);
                mma16816(acc[1][2*ctp],   a10,a11,a12,a13, w0,w1);
                mma16816(acc[1][2*ctp+1], a10,a11,a12,a13, w2,w3);
            }
        }
    }
    __syncthreads();

    float ssq[2][2] = {{0.f,0.f},{0.f,0.f}};
    #pragma unroll
    for (int mt = 0; mt < 2; mt++)
        #pragma unroll
        for (int ct = 0; ct < 8; ct++){
            int ch = (wc4 << 6) + (ct << 3) + (l2 << 1);
            float2 bb = *(const float2*)(bias + ch);
            acc[mt][ct][0] += bb.x; acc[mt][ct][1] += bb.y;
            acc[mt][ct][2] += bb.x; acc[mt][ct][3] += bb.y;
            if (which < 2){
                ssq[mt][0] += acc[mt][ct][0]*acc[mt][ct][0] + acc[mt][ct][1]*acc[mt][ct][1];
                ssq[mt][1] += acc[mt][ct][2]*acc[mt][ct][2] + acc[mt][ct][3]*acc[mt][ct][3];
            }
        }

    if (which < 2){
        #pragma unroll
        for (int mt = 0; mt < 2; mt++)
            #pragma unroll
            for (int h = 0; h < 2; h++){
                float v = ssq[mt][h];
                v += __shfl_xor_sync(0xffffffffu, v, 1);
                v += __shfl_xor_sync(0xffffffffu, v, 2);
                ssq[mt][h] = v;
            }
        float* ssm = (float*)smem;    // [4][64]
        if (l2 == 0){
            #pragma unroll
            for (int mt = 0; mt < 2; mt++){
                int rl = (wq2 << 5) + (mt << 4) + l4;
                ssm[wc4*64 + rl]     = ssq[mt][0];
                ssm[wc4*64 + rl + 8] = ssq[mt][1];
            }
        }
        __syncthreads();
        const float qsc = (which == 0) ? L2E : 1.f;
        __half* O = (which == 0) ? g_Qh : g_Kh;
        #pragma unroll
        for (int mt = 0; mt < 2; mt++){
            int rl = (wq2 << 5) + (mt << 4) + l4;
            float scl = rsqrtf(ssm[rl] + ssm[64+rl] + ssm[128+rl] + ssm[192+rl] + 1e-12f) * qsc;
            int rh = rl + 8;
            float sch = rsqrtf(ssm[rh] + ssm[64+rh] + ssm[128+rh] + ssm[192+rh] + 1e-12f) * qsc;
            #pragma unroll
            for (int ct = 0; ct < 8; ct++){
                int ch = (wc4 << 6) + (ct << 3) + (l2 << 1);
                __half2 h = __floats2half2_rn(acc[mt][ct][0]*scl, acc[mt][ct][1]*scl);
                *(uint32_t*)(O + (size_t)(tm + rl)*C_ + ch) = *(uint32_t*)&h;
                h = __floats2half2_rn(acc[mt][ct][2]*sch, acc[mt][ct][3]*sch);
                *(uint32_t*)(O + (size_t)(tm + rh)*C_ + ch) = *(uint32_t*)&h;
            }
        }
    } else {
        __half* T = (__half*)smem;    // [64][264]
        #pragma unroll
        for (int mt = 0; mt < 2; mt++){
            int rl = (wq2 << 5) + (mt << 4) + l4, rh = rl + 8;
            #pragma unroll
            for (int ct = 0; ct < 8; ct++){
                int ch = (wc4 << 6) + (ct << 3) + (l2 << 1);
                __half2 h = __floats2half2_rn(acc[mt][ct][0], acc[mt][ct][1]);
                *(uint32_t*)&T[rl*264 + ch] = *(uint32_t*)&h;
                h = __floats2half2_rn(acc[mt][ct][2], acc[mt][ct][3]);
                *(uint32_t*)&T[rh*264 + ch] = *(uint32_t*)&h;
            }
        }
        __syncthreads();
        const int c = tid;
        const int n0 = tm & (N_ - 1);
        __half* Ov = g_VTh + ((size_t)(b*C_ + c))*N_ + n0;
        #pragma unroll
        for (int j = 0; j < 8; j++){
            __half hh[8];
            #pragma unroll
            for (int i = 0; i < 8; i++) hh[i] = T[(j*8 + i)*264 + c];
            *(uint4*)(Ov + j*8) = *(uint4*)hh;
        }
    }
}

// ---------------- HMMA fused attention + AdaIN (R12 config) ----------------
// Q hoist + fp16-accum phase A, fp32 accM/accV2.
// CTA = 64 queries x 256 channels x all 4096 keys. 256 threads (8 warps).
__global__ __launch_bounds__(256, 1) void k_attn_mma(const float* __restrict__ content,
                                                     float* __restrict__ out){
    extern __shared__ char sm[];
    const uint32_t sb = s2u(sm);
    const int tid = threadIdx.x, warp = tid >> 5, lane = tid & 31;
    const int q0 = blockIdx.x << 6;
    const int b  = q0 >> 12;
    const int wq = warp & 3, wk2 = warp >> 2;        // phase A tiling (16q x 32k)
    const int wq2 = warp >> 2, wc4 = warp & 3;       // phase B tiling (32q x 64ch)
    const int mi = lane >> 3, r8 = lane & 7;
    const int l4 = lane >> 2, l2 = lane & 3;

    const __half* vt_base = g_VTh + (size_t)b*C_*N_;
    const uint32_t aA     = sb + QS_OFF + (uint32_t)((wq << 4) + r8 + ((mi & 1) << 3))*512;
    const uint32_t aB_off = (uint32_t)((wk2 << 5) + r8 + ((mi >> 1) << 3))*512;
    const uint32_t pB_off = (uint32_t)((wq2 << 5) + r8 + ((mi & 1) << 3))*128;
    const uint32_t vB_off = (uint32_t)((wc4 << 6) + r8 + ((mi >> 1) << 3))*128;

    float accM[2][8][4], accV2[2][8][4];
    #pragma unroll
    for (int mt = 0; mt < 2; mt++)
        #pragma unroll
        for (int ct = 0; ct < 8; ct++)
            #pragma unroll
            for (int j = 0; j < 4; j++){ accM[mt][ct][j] = 0.f; accV2[mt][ct][j] = 0.f; }
    float z0 = 0.f, z1 = 0.f;

    auto loadK = [&](int kt, int buf){
        uint32_t kdst = sb + KS_OFF + buf*32768;
        for (int it = tid; it < 2048; it += 256){
            int r = it >> 5, c16 = it & 31;
            cpa16(kdst + r*512 + (((uint32_t)(c16 ^ (r & 7))) << 4),
                  g_Kh + (((size_t)((b << 12) + (kt << 6) + r)) << 8) + (c16 << 3));
        }
    };
    auto loadVT = [&](int kt, int buf){
        uint32_t vdst = sb + VTS_OFF + buf*32768;
        for (int it = tid; it < 2048; it += 256){
            int r = it >> 3, c16 = it & 7;
            cpa16(vdst + r*128 + (((uint32_t)(c16 ^ (r & 7))) << 4),
                  vt_base + (((size_t)r) << 12) + (kt << 6) + (c16 << 3));
        }
    };
    // fp16 logits dd[nt][0]=rows r, dd[nt][1]=rows r+8 -> exp -> P store
    auto expStore = [&](uint32_t dd[4][2], int j){
        char* pb = sm + PS_OFF + (j & 1)*8192;
        const int qlo = (wq << 4) + l4;
        #pragma unroll
        for (int nt = 0; nt < 4; nt++){
            uint32_t plo = ex2h2(dd[nt][0]);
            uint32_t phi = ex2h2(dd[nt][1]);
            z0 += hsum2(plo);
            z1 += hsum2(phi);
            int c16p = (wk2 << 2) + nt;
            uint32_t sw = ((uint32_t)(c16p ^ l4)) << 4;
            *(uint32_t*)(pb + qlo*128 + sw + (l2 << 2))       = plo;
            *(uint32_t*)(pb + (qlo + 8)*128 + sw + (l2 << 2)) = phi;
        }
    };
    auto phaseBs = [&](uint32_t aPb, uint32_t aVb, int s){
        uint32_t colA = ((uint32_t)((2*s + (mi >> 1)) ^ r8)) << 4;
        uint32_t p00,p01,p02,p03, p10,p11,p12,p13;
        ldm4(aPb + colA, p00,p01,p02,p03);
        ldm4(aPb + 16*128 + colA, p10,p11,p12,p13);
        uint32_t colB = ((uint32_t)((2*s + (mi & 1)) ^ r8)) << 4;
        #pragma unroll
        for (int ctp = 0; ctp < 4; ctp++){
            uint32_t v0,v1,v2,v3;
            ldm4(aVb + (uint32_t)(ctp << 4)*128 + colB, v0,v1,v2,v3);
            mma16816(accM[0][2*ctp],   p00,p01,p02,p03, v0,v1);
            mma16816(accM[0][2*ctp+1], p00,p01,p02,p03, v2,v3);
            mma16816(accM[1][2*ctp],   p10,p11,p12,p13, v0,v1);
            mma16816(accM[1][2*ctp+1], p10,p11,p12,p13, v2,v3);
            uint32_t w0 = sqr2(v0), w1 = sqr2(v1), w2 = sqr2(v2), w3 = sqr2(v3);
            mma16816(accV2[0][2*ctp],   p00,p01,p02,p03, w0,w1);
            mma16816(accV2[0][2*ctp+1], p00,p01,p02,p03, w2,w3);
            mma16816(accV2[1][2*ctp],   p10,p11,p12,p13, w0,w1);
            mma16816(accV2[1][2*ctp+1], p10,p11,p12,p13, w2,w3);
        }
    };

    // ---- prologue ----
    for (int it = tid; it < 2048; it += 256){
        int r = it >> 5, c16 = it & 31;
        cpa16(sb + QS_OFF + r*512 + (((uint32_t)(c16 ^ (r & 7))) << 4),
              g_Qh + (((size_t)(q0 + r)) << 8) + (c16 << 3));
    }
    loadK(0, 0);
    CPCOMMIT();                 // G0: Q + K(0)
    loadVT(0, 0);
    loadK(1, 1);
    CPCOMMIT();                 // G1: VT(0) + K(1)
    CPWAIT(1);                  // G0 complete
    __syncthreads();

    // hoist Q fragments (live across all tiles)
    uint32_t qf[16][4];
    #pragma unroll
    for (int cs = 0; cs < 16; cs++)
        ldm4(aA + (((uint32_t)((2*cs + (mi >> 1)) ^ r8)) << 4),
             qf[cs][0], qf[cs][1], qf[cs][2], qf[cs][3]);

    {   // phase A(0) -> P[0]  (fp16 accumulation)
        const uint32_t kb0 = sb + KS_OFF + aB_off;
        uint32_t dd[4][2];
        #pragma unroll
        for (int i = 0; i < 4; i++){ dd[i][0] = 0u; dd[i][1] = 0u; }
        #pragma unroll
        for (int cs = 0; cs < 16; cs++){
            uint32_t b0,b1,b2,b3;
            uint32_t cB = ((uint32_t)((2*cs + (mi & 1)) ^ r8)) << 4;
            ldm4(kb0 + cB, b0,b1,b2,b3);
            mma16816h(dd[0], qf[cs][0], qf[cs][1], qf[cs][2], qf[cs][3], b0,b1);
            mma16816h(dd[1], qf[cs][0], qf[cs][1], qf[cs][2], qf[cs][3], b2,b3);
            ldm4(kb0 + 16*512 + cB, b0,b1,b2,b3);
            mma16816h(dd[2], qf[cs][0], qf[cs][1], qf[cs][2], qf[cs][3], b0,b1);
            mma16816h(dd[3], qf[cs][0], qf[cs][1], qf[cs][2], qf[cs][3], b2,b3);
        }
        expStore(dd, 0);
    }

    // ---- main loop: 63 fused iterations, A(i+1) interleaved with B(i) ----
    for (int i = 0; i < 63; i++){
        CPWAIT(0);              // K(i+1), VT(i) complete
        __syncthreads();        // load visibility + P(i) stores + buffer reuse
        if (i < 62) loadK(i + 2, i & 1);
        loadVT(i + 1, (i + 1) & 1);
        CPCOMMIT();

        const uint32_t kb0 = sb + KS_OFF + ((i + 1) & 1)*32768 + aB_off;
        const uint32_t aPb = sb + PS_OFF  + (i & 1)*8192  + pB_off;
        const uint32_t aVb = sb + VTS_OFF + (i & 1)*32768 + vB_off;
        uint32_t dd[4][2];
        #pragma unroll
        for (int k = 0; k < 4; k++){ dd[k][0] = 0u; dd[k][1] = 0u; }

        #pragma unroll
        for (int s = 0; s < 4; s++){
            // -- A chunk: k-steps 4s..4s+3 on K[(i+1)&1] (Q frags in regs) --
            #pragma unroll
            for (int c = 0; c < 4; c++){
                const int cs = 4*s + c;
                uint32_t b0,b1,b2,b3;
                uint32_t cB = ((uint32_t)((2*cs + (mi & 1)) ^ r8)) << 4;
                ldm4(kb0 + cB, b0,b1,b2,b3);
                mma16816h(dd[0], qf[cs][0], qf[cs][1], qf[cs][2], qf[cs][3], b0,b1);
                mma16816h(dd[1], qf[cs][0], qf[cs][1], qf[cs][2], qf[cs][3], b2,b3);
                ldm4(kb0 + 16*512 + cB, b0,b1,b2,b3);
                mma16816h(dd[2], qf[cs][0], qf[cs][1], qf[cs][2], qf[cs][3], b0,b1);
                mma16816h(dd[3], qf[cs][0], qf[cs][1], qf[cs][2], qf[cs][3], b2,b3);
            }
            // -- B chunk s: P[i&1] x VT[i&1] (independent stream) --
            phaseBs(aPb, aVb, s);
        }
        expStore(dd, i + 1);    // P[(i+1)&1]
    }

    // ---- final tile: B(63) only ----
    CPWAIT(0);
    __syncthreads();
    {
        const uint32_t aPb = sb + PS_OFF  + (63 & 1)*8192  + pB_off;
        const uint32_t aVb = sb + VTS_OFF + (63 & 1)*32768 + vB_off;
        #pragma unroll
        for (int s = 0; s < 4; s++) phaseBs(aPb, aVb, s);
    }
    __syncthreads();            // P buffers free for Z exchange

    // ---- Z exchange: reduce over l2 lanes, then across wk2 via smem ----
    z0 += __shfl_xor_sync(0xffffffffu, z0, 1);
    z0 += __shfl_xor_sync(0xffffffffu, z0, 2);
    z1 += __shfl_xor_sync(0xffffffffu, z1, 1);
    z1 += __shfl_xor_sync(0xffffffffu, z1, 2);
    float* Zs = (float*)(sm + PS_OFF);      // [64][2]
    if (l2 == 0){
        Zs[(((wq << 4) + l4) << 1) + wk2]     = z0;
        Zs[(((wq << 4) + l4 + 8) << 1) + wk2] = z1;
    }
    __syncthreads();

    // ---- epilogue: M/S2, AdaIN, store ----
    const float* meanp = g_mean + b*C_;
    const float* rstdp = g_rstd + b*C_;
    #pragma unroll
    for (int mt = 0; mt < 2; mt++){
        const int rloc = (wq2 << 5) + (mt << 4) + l4;
        const float izlo = 1.f / (Zs[rloc << 1] + Zs[(rloc << 1) + 1]);
        const float izhi = 1.f / (Zs[(rloc + 8) << 1] + Zs[((rloc + 8) << 1) + 1]);
        const int rl = q0 + rloc;
        const size_t glo = ((size_t)rl) << 8;
        const size_t ghi = ((size_t)(rl + 8)) << 8;
        #pragma unroll
        for (int ct = 0; ct < 8; ct++){
            const int ch = (wc4 << 6) + (ct << 3) + (l2 << 1);
            const float mn0 = meanp[ch], mn1 = meanp[ch+1];
            const float rs0 = rstdp[ch], rs1 = rstdp[ch+1];
            {
                float2 cv = *(const float2*)(content + glo + ch);
                float m = accM[mt][ct][0]*izlo;
                float s2 = accV2[mt][ct][0]*izlo - m*m;
                float s = s2 > 0.f ? sqrtf(s2) : 0.f;
                float2 o;
                o.x = s*((cv.x - mn0)*rs0) + m;
                m = accM[mt][ct][1]*izlo;
                s2 = accV2[mt][ct][1]*izlo - m*m;
                s = s2 > 0.f ? sqrtf(s2) : 0.f;
                o.y = s*((cv.y - mn1)*rs1) + m;
                *(float2*)(out + glo + ch) = o;
            }
            {
                float2 cv = *(const float2*)(content + ghi + ch);
                float m = accM[mt][ct][2]*izhi;
                float s2 = accV2[mt][ct][2]*izhi - m*m;
                float s = s2 > 0.f ? sqrtf(s2) : 0.f;
                float2 o;
                o.x = s*((cv.x - mn0)*rs0) + m;
                m = accM[mt][ct][3]*izhi;
                s2 = accV2[mt][ct][3]*izhi - m*m;
                s = s2 > 0.f ? sqrtf(s2) : 0.f;
                o.y = s*((cv.y - mn1)*rs1) + m;
                *(float2*)(out + ghi + ch) = o;
            }
        }
    }
}

// ---------------- launch ----------------
extern "C" void kernel_launch(void* const* d_in, const int* in_sizes, int n_in,
                              void* d_out, int out_size){
    const float* content = (const float*)d_in[0];
    const float* style   = (const float*)d_in[1];
    const float* Wq = (const float*)d_in[2];
    const float* bq = (const float*)d_in[3];
    const float* Wk = (const float*)d_in[4];
    const float* bk = (const float*)d_in[5];
    const float* Wv = (const float*)d_in[6];
    const float* bv = (const float*)d_in[7];
    float* out = (float*)d_out;

    cudaFuncSetAttribute(k_attn_mma, cudaFuncAttributeMaxDynamicSharedMemorySize, SMEM_ATT);

    k_stats_partial<<<dim3(NSPLIT, B_, 2), 256>>>(content, style);
    k_stats_final<<<dim3(B_, 2), 256>>>();
    k_wcvt<<<dim3(8, 8, 3), dim3(32, 8)>>>(Wq, Wk, Wv);
    k_qkv<<<dim3(M_/64, 3), 256>>>(content, style, bq, bk, bv);
    k_attn_mma<<<M_/64, 256, SMEM_ATT>>>(content, out);
}